// round 4
// baseline (speedup 1.0000x reference)
#include <cuda_runtime.h>

#define D_MODEL 64
#define N_CODES 2048
#define MAXCAND 12

// scratch (no device allocation allowed)
__device__ float  g_colsum[N_CODES];
__device__ double g_losssum;

typedef unsigned long long ull;

__device__ __forceinline__ void fma2(ull &d, ull a, ull b) {
    asm("fma.rn.f32x2 %0, %1, %2, %0;" : "+l"(d) : "l"(a), "l"(b));
}
__device__ __forceinline__ ull pack2(float lo, float hi) {
    ull r; asm("mov.b64 %0, {%1, %2};" : "=l"(r) : "f"(lo), "f"(hi)); return r;
}
__device__ __forceinline__ float2 unpack2(ull v) {
    float2 r; asm("mov.b64 {%0, %1}, %2;" : "=f"(r.x), "=f"(r.y) : "l"(v)); return r;
}

// ---------------------------------------------------------------------------
// Kernel 0: colsum[k] = sum_d emb[k][d]^2 (serial mul+add — bit-proven R3)
// ---------------------------------------------------------------------------
__global__ void prep_kernel(const float* __restrict__ emb) {
    int k = blockIdx.x * blockDim.x + threadIdx.x;
    if (k == 0) g_losssum = 0.0;
    if (k < N_CODES) {
        const float* e = emb + (size_t)k * D_MODEL;
        float s = 0.f;
        #pragma unroll
        for (int d = 0; d < D_MODEL; ++d)
            s = __fadd_rn(s, __fmul_rn(e[d], e[d]));
        g_colsum[k] = s;
    }
}

// ---------------------------------------------------------------------------
// Exact w for one (row, code): correctly-rounded fp32 dot via fp64 (products
// of two f32 are exact in f64), then the proven epilogue double-rounding.
// ---------------------------------------------------------------------------
__device__ __forceinline__ float exact_w(const ull* xp, const float* __restrict__ E,
                                         int code, float rsum) {
    const float4* Er = (const float4*)E + (size_t)code * 16;
    double a0 = 0.0, a1 = 0.0;
    #pragma unroll
    for (int q = 0; q < 16; ++q) {
        float4 e = Er[q];
        float2 x0 = unpack2(xp[2 * q]);
        float2 x1 = unpack2(xp[2 * q + 1]);
        a0 = __fma_rn((double)x0.x, (double)e.x, a0);
        a1 = __fma_rn((double)x0.y, (double)e.y, a1);
        a0 = __fma_rn((double)x1.x, (double)e.z, a0);
        a1 = __fma_rn((double)x1.y, (double)e.w, a1);
    }
    float dotf = (float)(a0 + a1);          // correctly-rounded fp32 dot
    return __fadd_rn(__fmaf_rn(-2.f, dotf, rsum), g_colsum[code]);
}

// ---------------------------------------------------------------------------
// Main kernel: one thread per row.
//   fast pass: f32x2-packed dots, candidate window capture
//   recheck:   exact fp64 for candidates, lexicographic (w, idx) argmin
//   fused gather + z_q_st + fp64 loss + idx output (proven R3 code)
// ---------------------------------------------------------------------------
__global__ void __launch_bounds__(128, 4)
vq_main_kernel(const float* __restrict__ X, const float* __restrict__ E,
               float* __restrict__ out, int NR, int has_extras) {
    extern __shared__ float sh[];
    float4* Es4 = (float4*)sh;          // [128 codes][16 quads]
    float*  cs  = sh + 128 * D_MODEL;   // [128] colsums

    const int tid = threadIdx.x;
    const long row = (long)blockIdx.x * 128 + tid;

    // ---- load x row, pack into 32 f32x2 registers ----
    ull xp[32];
    const float4* Xg = (const float4*)X + row * 16;
    #pragma unroll
    for (int q = 0; q < 16; ++q) {
        float4 v = Xg[q];
        xp[2 * q]     = pack2(v.x, v.y);
        xp[2 * q + 1] = pack2(v.z, v.w);
    }

    // ---- rowsum: serial mul+add d = 0..63 (bit-proven) ----
    float rsum = 0.f;
    #pragma unroll
    for (int q = 0; q < 16; ++q) {
        float2 x0 = unpack2(xp[2 * q]);
        float2 x1 = unpack2(xp[2 * q + 1]);
        rsum = __fadd_rn(rsum, __fmul_rn(x0.x, x0.x));
        rsum = __fadd_rn(rsum, __fmul_rn(x0.y, x0.y));
        rsum = __fadd_rn(rsum, __fmul_rn(x1.x, x1.x));
        rsum = __fadd_rn(rsum, __fmul_rn(x1.y, x1.y));
    }

    float bestv = __int_as_float(0x7f800000);   // +inf (approx running min)
    int   cand[MAXCAND];
    int   ncand = 0;

    for (int t = 0; t < N_CODES / 128; ++t) {
        __syncthreads();
        const float4* Eg = (const float4*)E + (size_t)t * 128 * 16;
        #pragma unroll
        for (int it = 0; it < 16; ++it)
            Es4[tid + it * 128] = Eg[tid + it * 128];
        cs[tid] = g_colsum[t * 128 + tid];
        __syncthreads();

        #pragma unroll 1
        for (int c0 = 0; c0 < 128; c0 += 4) {
            ull a0 = 0ull, a1 = 0ull, a2 = 0ull, a3 = 0ull;
            #pragma unroll
            for (int q = 0; q < 16; ++q) {
                const ulonglong2 e0 = *(const ulonglong2*)(Es4 + (c0 + 0) * 16 + q);
                const ulonglong2 e1 = *(const ulonglong2*)(Es4 + (c0 + 1) * 16 + q);
                const ulonglong2 e2 = *(const ulonglong2*)(Es4 + (c0 + 2) * 16 + q);
                const ulonglong2 e3 = *(const ulonglong2*)(Es4 + (c0 + 3) * 16 + q);
                const ull xa = xp[2 * q], xb = xp[2 * q + 1];
                fma2(a0, xa, e0.x); fma2(a0, xb, e0.y);
                fma2(a1, xa, e1.x); fma2(a1, xb, e1.y);
                fma2(a2, xa, e2.x); fma2(a2, xb, e2.y);
                fma2(a3, xa, e3.x); fma2(a3, xb, e3.y);
            }
            const int cb = t * 128 + c0;
            #pragma unroll
            for (int j = 0; j < 4; ++j) {
                ull aj = (j == 0) ? a0 : (j == 1) ? a1 : (j == 2) ? a2 : a3;
                float2 p = unpack2(aj);
                float dot = __fadd_rn(p.x, p.y);
                float w = __fadd_rn(__fmaf_rn(-2.f, dot, rsum), cs[c0 + j]);
                // capture window: >= 8 ulp above running best (provably safe)
                if (w <= bestv * 1.000001f) {
                    if (ncand < MAXCAND) cand[ncand] = cb + j;
                    ++ncand;
                }
                if (w < bestv) bestv = w;
            }
        }
    }

    // ---- exact recheck over candidates (lexicographic (w, idx) min) ----
    float bw = __int_as_float(0x7f800000);
    int   besti = 0;
    if (ncand <= MAXCAND) {
        for (int j = 0; j < ncand; ++j) {          // ascending idx order
            int c = cand[j];
            float w = exact_w(xp, E, c, rsum);
            if (w < bw) { bw = w; besti = c; }
        }
    } else {                                       // overflow: full exact row
        for (int c = 0; c < N_CODES; ++c) {
            float w = exact_w(xp, E, c, rsum);
            if (w < bw) { bw = w; besti = c; }
        }
    }

    // ---- fused gather: z_q_st = fl(ze + fl(e - ze)), fp64 loss partial ----
    const float4* Ee = (const float4*)E + (size_t)besti * 16;
    float4* Og = (float4*)out + row * 16;
    double ls = 0.0;
    #pragma unroll
    for (int q = 0; q < 16; ++q) {
        float2 x0 = unpack2(xp[2 * q]);
        float2 x1 = unpack2(xp[2 * q + 1]);
        const float4 ev = Ee[q];
        float dx = __fsub_rn(ev.x, x0.x);
        float dy = __fsub_rn(ev.y, x0.y);
        float dz = __fsub_rn(ev.z, x1.x);
        float dw = __fsub_rn(ev.w, x1.y);
        float4 o;
        o.x = __fadd_rn(x0.x, dx);
        o.y = __fadd_rn(x0.y, dy);
        o.z = __fadd_rn(x1.x, dz);
        o.w = __fadd_rn(x1.y, dw);
        Og[q] = o;
        ls += (double)dx * dx + (double)dy * dy
            + (double)dz * dz + (double)dw * dw;
    }
    #pragma unroll
    for (int off = 16; off; off >>= 1)
        ls += __shfl_down_sync(0xffffffffu, ls, off);
    if ((tid & 31) == 0) atomicAdd(&g_losssum, ls);

    if (has_extras)
        out[(size_t)NR * D_MODEL + 1 + row] = (float)besti;
}

// ---------------------------------------------------------------------------
__global__ void finalize_kernel(float* __restrict__ out, int NR) {
    double m = g_losssum / (double)((size_t)NR * D_MODEL);
    float mf = (float)m;
    out[(size_t)NR * D_MODEL] = __fadd_rn(__fmul_rn(0.25f, mf), mf);
}

// ---------------------------------------------------------------------------
extern "C" void kernel_launch(void* const* d_in, const int* in_sizes, int n_in,
                              void* d_out, int out_size) {
    (void)n_in;
    const float* ze;
    const float* emb;
    int nz;
    if (in_sizes[0] >= in_sizes[1]) {
        ze = (const float*)d_in[0]; emb = (const float*)d_in[1]; nz = in_sizes[0];
    } else {
        ze = (const float*)d_in[1]; emb = (const float*)d_in[0]; nz = in_sizes[1];
    }
    const int NR = nz / D_MODEL;          // 131072 rows

    float* out = (float*)d_out;
    const int has_extras = (out_size >= NR * D_MODEL + 1 + NR) ? 1 : 0;

    const int SMEM_BYTES = 128 * D_MODEL * 4 + 128 * 4;   // 33280

    prep_kernel<<<(N_CODES + 127) / 128, 128>>>(emb);
    vq_main_kernel<<<NR / 128, 128, SMEM_BYTES>>>(ze, emb, out, NR, has_extras);
    if (out_size > NR * D_MODEL)
        finalize_kernel<<<1, 1>>>(out, NR);
}